// round 12
// baseline (speedup 1.0000x reference)
#include <cuda_runtime.h>
#include <cuda_bf16.h>
#include <math_constants.h>

#define NN 20000
#define EE 640000

#define SC_DOT 1.6329931618554521f     // sqrt(8/3)
#define SC_B   0.5773502691896258f     // sqrt(1/3)
#define SC_V   (-0.04811252243246881f) // -0.5*sqrt(1/108)

// ---- device scratch ----
__device__ __align__(16) float g_proj[(size_t)NN * 800]; // qs[0:256) ks[256:512) qv[512:608) kv[608:704) vv[704:800)
__device__ __align__(16) float g_qv[(size_t)NN * 96];
__device__ __align__(16) float g_kv[(size_t)NN * 96];
__device__ __align__(16) float g_zd[(size_t)EE * 20];    // CSR-ordered: [bias(4) | pz(16)] per edge
__device__ int   g_cnt[NN];
__device__ int   g_off[NN];
__device__ int   g_cur[NN];
__device__ int   g_pos[EE];      // e -> CSR slot
__device__ int   g_jsort[EE];    // CSR slot -> j
__device__ __align__(16) float g_fin[(size_t)NN * 160];  // [s(64) | norm(32) | pair(64)]
__device__ __align__(16) float g_Bproj[64 * 800];
__device__ __align__(16) float g_wcat[160 * 64];

// ---- merged setup: init counters + pack proj weights + fuse output weights ----
__global__ void k_setup(const float* __restrict__ Wq_s, const float* __restrict__ Wk_s,
                        const float* __restrict__ Wq_v, const float* __restrict__ Wk_v,
                        const float* __restrict__ Wv_v, const float* __restrict__ Wv_s,
                        const float* __restrict__ Wout) {
    int idx = blockIdx.x * blockDim.x + threadIdx.x;
    if (idx < NN) { g_cnt[idx] = 0; g_cur[idx] = 0; }
    if (idx < 64 * 800) {
        int d = idx / 800, c = idx % 800;
        float v;
        if (c < 256)      v = Wq_s[d * 256 + c];
        else if (c < 512) v = Wk_s[d * 256 + (c - 256)];
        else if (c < 608) v = Wq_v[d * 96 + (c - 512)];
        else if (c < 704) v = Wk_v[d * 96 + (c - 608)];
        else              v = Wv_v[d * 96 + (c - 704)];
        g_Bproj[idx] = v;
    }
    if (idx < 160 * 64) {
        int r = idx >> 6, c = idx & 63;
        if (r < 64) {
            float acc = 0.f;
            for (int k = 0; k < 256; k++) acc += Wv_s[r * 256 + k] * Wout[k * 64 + c];
            for (int k = 0; k < 96; k++)  acc += Wv_v[r * 96 + k] * Wout[(256 + k) * 64 + c];
            g_wcat[idx] = acc;
        } else if (r < 96) {
            g_wcat[idx] = Wout[(352 + (r - 64)) * 64 + c];
        } else {
            g_wcat[idx] = Wout[(384 + (r - 96)) * 64 + c];
        }
    }
}

__global__ void k_count(const int* __restrict__ ei, int E) {
    int e = blockIdx.x * blockDim.x + threadIdx.x;
    if (e < E) atomicAdd(&g_cnt[ei[e]], 1);
}

__global__ void k_scan(int n) {
    __shared__ int wsum[32];
    int tid = threadIdx.x;
    int per = (n + 1023) / 1024;
    int base = tid * per;
    int s = 0;
    for (int k = 0; k < per; k++) { int idx = base + k; if (idx < n) s += g_cnt[idx]; }
    int lane = tid & 31, w = tid >> 5;
    int v = s;
    #pragma unroll
    for (int o = 1; o < 32; o <<= 1) { int t = __shfl_up_sync(~0u, v, o); if (lane >= o) v += t; }
    if (lane == 31) wsum[w] = v;
    __syncthreads();
    if (w == 0) {
        int orig = wsum[lane], x = orig;
        #pragma unroll
        for (int o = 1; o < 32; o <<= 1) { int t = __shfl_up_sync(~0u, x, o); if (lane >= o) x += t; }
        wsum[lane] = x - orig;
    }
    __syncthreads();
    int run = v - s + wsum[w];
    for (int k = 0; k < per; k++) {
        int idx = base + k;
        if (idx < n) { g_off[idx] = run; run += g_cnt[idx]; }
    }
}

__global__ void k_scatter(const int* __restrict__ ei, const int* __restrict__ ej, int E) {
    int e = blockIdx.x * blockDim.x + threadIdx.x;
    if (e < E) {
        int i = ei[e];
        int p = atomicAdd(&g_cur[i], 1);
        int pos = g_off[i] + p;
        g_pos[e] = pos;
        g_jsort[pos] = ej[e];
    }
}

// ---- projection GEMM: g_proj[M,800] = s[M,64] @ g_Bproj[64,800] ----
__global__ void __launch_bounds__(256) k_gemm_proj(const float* __restrict__ A, int M) {
    __shared__ float4 As4[128][16];
    __shared__ float4 Bs4[64][16];
    const float* B = g_Bproj;
    int tid = threadIdx.x;
    int tx = tid & 15, ty = tid >> 4;
    int row0 = blockIdx.y * 128, col0 = blockIdx.x * 64;

    for (int i = tid; i < 128 * 16; i += 256) {
        int r = i >> 4, kq = i & 15;
        int gr = row0 + r;
        float4 av = make_float4(0.f, 0.f, 0.f, 0.f);
        if (gr < M) av = *(const float4*)(A + (size_t)gr * 64 + kq * 4);
        As4[r][kq] = av;
    }
    for (int i = tid; i < 64 * 16; i += 256) {
        int k = i >> 4, cq = i & 15;
        int gc = col0 + cq * 4;
        float4 bv = make_float4(0.f, 0.f, 0.f, 0.f);
        if (gc < 800) bv = *(const float4*)(B + (size_t)k * 800 + gc);
        Bs4[k][cq] = bv;
    }
    __syncthreads();

    float acc[8][4] = {};
    #pragma unroll
    for (int kq = 0; kq < 16; kq++) {
        float4 b0 = Bs4[kq * 4 + 0][tx];
        float4 b1 = Bs4[kq * 4 + 1][tx];
        float4 b2 = Bs4[kq * 4 + 2][tx];
        float4 b3 = Bs4[kq * 4 + 3][tx];
        #pragma unroll
        for (int i = 0; i < 8; i++) {
            float4 a = As4[ty * 8 + i][kq];
            acc[i][0] += a.x * b0.x + a.y * b1.x + a.z * b2.x + a.w * b3.x;
            acc[i][1] += a.x * b0.y + a.y * b1.y + a.z * b2.y + a.w * b3.y;
            acc[i][2] += a.x * b0.z + a.y * b1.z + a.z * b2.z + a.w * b3.z;
            acc[i][3] += a.x * b0.w + a.y * b1.w + a.z * b2.w + a.w * b3.w;
        }
    }
    int gc = col0 + tx * 4;
    if (gc < 800) {
        #pragma unroll
        for (int i = 0; i < 8; i++) {
            int gr = row0 + ty * 8 + i;
            if (gr < M) {
                *(float4*)(g_proj + (size_t)gr * 800 + gc) =
                    make_float4(acc[i][0], acc[i][1], acc[i][2], acc[i][3]);
            }
        }
    }
}

// ---- output GEMM: out[M,64] = g_fin[M,160] @ g_wcat[160,64] + bout ----
__global__ void k_gemm_out(const float* __restrict__ bout, float* __restrict__ out, int M) {
    __shared__ __align__(16) float As[64][17];
    __shared__ __align__(16) float Bs[16][64];
    const float* A = g_fin;
    const float* B = g_wcat;
    int tid = threadIdx.x;
    int tx = tid & 15, ty = tid >> 4;
    int row0 = blockIdx.y * 64;
    float acc[4][4] = {};
    int am = tid >> 2;
    int ak = (tid & 3) * 4;
    int bk = tid >> 6;
    int bn = tid & 63;

    for (int k0 = 0; k0 < 160; k0 += 16) {
        int gr = row0 + am;
        float4 av = make_float4(0.f, 0.f, 0.f, 0.f);
        if (gr < M) av = *(const float4*)(A + (size_t)gr * 160 + k0 + ak);
        As[am][ak + 0] = av.x; As[am][ak + 1] = av.y; As[am][ak + 2] = av.z; As[am][ak + 3] = av.w;
        #pragma unroll
        for (int l = 0; l < 4; l++) {
            int kk = bk + l * 4;
            Bs[kk][bn] = B[(size_t)(k0 + kk) * 64 + bn];
        }
        __syncthreads();
        #pragma unroll
        for (int kk = 0; kk < 16; kk++) {
            float a0 = As[ty * 4 + 0][kk], a1 = As[ty * 4 + 1][kk];
            float a2 = As[ty * 4 + 2][kk], a3 = As[ty * 4 + 3][kk];
            float4 bv = *(const float4*)&Bs[kk][tx * 4];
            acc[0][0] += a0 * bv.x; acc[0][1] += a0 * bv.y; acc[0][2] += a0 * bv.z; acc[0][3] += a0 * bv.w;
            acc[1][0] += a1 * bv.x; acc[1][1] += a1 * bv.y; acc[1][2] += a1 * bv.z; acc[1][3] += a1 * bv.w;
            acc[2][0] += a2 * bv.x; acc[2][1] += a2 * bv.y; acc[2][2] += a2 * bv.z; acc[2][3] += a2 * bv.w;
            acc[3][0] += a3 * bv.x; acc[3][1] += a3 * bv.y; acc[3][2] += a3 * bv.z; acc[3][3] += a3 * bv.w;
        }
        __syncthreads();
    }
    #pragma unroll
    for (int i = 0; i < 4; i++) {
        int gr = row0 + ty * 4 + i;
        if (gr >= M) continue;
        #pragma unroll
        for (int j = 0; j < 4; j++) {
            int gc = tx * 4 + j;
            out[(size_t)gr * 64 + gc] = acc[i][j] + bout[gc];
        }
    }
}

__global__ void k_rotate(const float* __restrict__ quat, const float* __restrict__ trans, int N) {
    int idx = blockIdx.x * blockDim.x + threadIdx.x;
    if (idx >= N * 64) return;
    int n = idx >> 6, t = idx & 63;
    int isQ = (t < 32);
    int c = t & 31;
    const float* src = g_proj + (size_t)n * 800 + (isQ ? 512 : 608);
    float vx = src[c], vy = src[32 + c], vz = src[64 + c];
    float qw = quat[n * 4 + 0], qx = quat[n * 4 + 1], qy = quat[n * 4 + 2], qz = quat[n * 4 + 3];
    float uvx = qy * vz - qz * vy;
    float uvy = qz * vx - qx * vz;
    float uvz = qx * vy - qy * vx;
    float rx = vx + 2.f * (qw * uvx + (qy * uvz - qz * uvy));
    float ry = vy + 2.f * (qw * uvy + (qz * uvx - qx * uvz));
    float rz = vz + 2.f * (qw * uvz + (qx * uvy - qy * uvx));
    float* dst = (isQ ? g_qv : g_kv) + (size_t)n * 96 + c * 3;
    dst[0] = rx + trans[n * 3 + 0];
    dst[1] = ry + trans[n * 3 + 1];
    dst[2] = rz + trans[n * 3 + 2];
}

// ---- z projections: bias(4 heads, scales folded) + pair_z(16), written at CSR pos ----
// warp per edge, grid-stride; all weights in registers
__global__ void __launch_bounds__(256) k_zproj(const float* __restrict__ z,
                       const float* __restrict__ Wb, const float* __restrict__ bb,
                       const float* __restrict__ Wdz, const float* __restrict__ bdz, int E) {
    int lane = threadIdx.x & 31;
    int gwarp = (blockIdx.x * blockDim.x + threadIdx.x) >> 5;
    int nwarp = (gridDim.x * blockDim.x) >> 5;
    int g = lane >> 3, r = lane & 7;
    int c16 = lane & 15, half = lane >> 4;

    // preload weights
    float wb[8];
    #pragma unroll
    for (int d = 0; d < 8; d++) wb[d] = Wb[(r * 8 + d) * 4 + g];
    float wd[32];
    #pragma unroll
    for (int d = 0; d < 32; d++) wd[d] = Wdz[(half * 32 + d) * 16 + c16];
    float bbg = SC_B * (bb[g]);
    float bdc = bdz[c16];

    for (int e = gwarp; e < E; e += nwarp) {
        int pos = g_pos[e];
        const float* zr = z + (size_t)e * 64;
        // bias: lane covers dims r*8..r*8+7 of head g
        float4 z0 = *(const float4*)(zr + r * 8);
        float4 z1 = *(const float4*)(zr + r * 8 + 4);
        float bias = z0.x * wb[0] + z0.y * wb[1] + z0.z * wb[2] + z0.w * wb[3]
                   + z1.x * wb[4] + z1.y * wb[5] + z1.z * wb[6] + z1.w * wb[7];
        bias += __shfl_xor_sync(~0u, bias, 1);
        bias += __shfl_xor_sync(~0u, bias, 2);
        bias += __shfl_xor_sync(~0u, bias, 4);
        // pz: lane covers dims half*32..+32, col c16
        float pc = 0.f;
        const float* zh = zr + half * 32;
        #pragma unroll
        for (int dq = 0; dq < 8; dq++) {
            float4 zv = *(const float4*)(zh + dq * 4);
            pc += zv.x * wd[dq * 4 + 0] + zv.y * wd[dq * 4 + 1]
                + zv.z * wd[dq * 4 + 2] + zv.w * wd[dq * 4 + 3];
        }
        pc += __shfl_xor_sync(~0u, pc, 16);
        float* rec = g_zd + (size_t)pos * 20;
        if (r == 0) rec[g] = SC_B * bias + bbg;
        if (lane < 16) rec[4 + c16] = pc + bdc;
    }
}

// ---- fused node kernel: warp per node, streaming online softmax + pair aggregation ----
__global__ void __launch_bounds__(256) k_nf(const float* __restrict__ s,
                                            const float* __restrict__ hw, int N) {
    int lane = threadIdx.x & 31, w = threadIdx.x >> 5;
    int n = blockIdx.x * 8 + w;
    if (n >= N) return;
    int off = g_off[n], deg = g_cnt[n];
    int g = lane >> 3, r = lane & 7;
    int c = lane & 15, hh = lane >> 4;

    // preload i-side data once per node
    const float* ksp = g_proj + (size_t)n * 800 + 256 + lane * 8;
    float4 k0 = *(const float4*)ksp;
    float4 k1 = *(const float4*)(ksp + 4);
    const float* qvp = g_qv + (size_t)n * 96 + lane * 3;
    float qvx = qvp[0], qvy = qvp[1], qvz = qvp[2];
    float svh = SC_V * log1pf(__expf(hw[g]));   // per-head softplus folded with scale

    // online softmax state: lane owns col c for heads hh and hh+2
    float m0 = -CUDART_INF_F, s0 = 0.f, P0 = 0.f;
    float m1 = -CUDART_INF_F, s1 = 0.f, P1 = 0.f;

    for (int t = 0; t < deg; t++) {
        int j = __ldg(&g_jsort[off + t]);
        // scalar dot partial
        const float* qsp = g_proj + (size_t)j * 800 + lane * 8;
        float4 q0 = *(const float4*)qsp;
        float4 q1 = *(const float4*)(qsp + 4);
        float part = k0.x * q0.x + k0.y * q0.y + k0.z * q0.z + k0.w * q0.w
                   + k1.x * q1.x + k1.y * q1.y + k1.z * q1.z + k1.w * q1.w;
        part *= SC_DOT;
        // point distance partial (point p = lane)
        const float* kvp = g_kv + (size_t)j * 96 + lane * 3;
        float dx = qvx - kvp[0], dy = qvy - kvp[1], dz = qvz - kvp[2];
        part += (dx * dx + dy * dy + dz * dz) * svh;
        // reduce within 8-lane head group
        part += __shfl_xor_sync(~0u, part, 1);
        part += __shfl_xor_sync(~0u, part, 2);
        part += __shfl_xor_sync(~0u, part, 4);
        // fetch logits for the two heads this lane accumulates
        const float* rec = g_zd + (size_t)(off + t) * 20;
        float l0 = __shfl_sync(~0u, part, hh * 8)       + __ldg(&rec[hh]);
        float l1 = __shfl_sync(~0u, part, (hh + 2) * 8) + __ldg(&rec[hh + 2]);
        float pz = __ldg(&rec[4 + c]);
        // online update head hh
        float mn0 = fmaxf(m0, l0);
        float sc0 = __expf(m0 - mn0), w0 = __expf(l0 - mn0);
        s0 = s0 * sc0 + w0; P0 = P0 * sc0 + w0 * pz; m0 = mn0;
        // online update head hh+2
        float mn1 = fmaxf(m1, l1);
        float sc1 = __expf(m1 - mn1), w1 = __expf(l1 - mn1);
        s1 = s1 * sc1 + w1; P1 = P1 * sc1 + w1 * pz; m1 = mn1;
    }
    float i0 = (s0 > 0.f) ? (1.f / s0) : 0.f;
    float i1 = (s1 > 0.f) ? (1.f / s1) : 0.f;

    float* fin = g_fin + (size_t)n * 160;
    fin[96 + hh * 16 + c] = P0 * i0;
    fin[96 + (hh + 2) * 16 + c] = P1 * i1;

    // s copy + vv point norms
    float2 sv = ((const float2*)(s + (size_t)n * 64))[lane];
    ((float2*)fin)[lane] = sv;
    const float* vv = g_proj + (size_t)n * 800 + 704;
    float px = vv[lane], py = vv[32 + lane], pz2 = vv[64 + lane];
    fin[64 + lane] = sqrtf(px * px + py * py + pz2 * pz2 + 1e-8f);
}

extern "C" void kernel_launch(void* const* d_in, const int* in_sizes, int n_in,
                              void* d_out, int out_size) {
    const float* s     = (const float*)d_in[0];
    const float* z     = (const float*)d_in[1];
    const int*   eidx  = (const int*)d_in[2];
    const float* quat  = (const float*)d_in[3];
    const float* trans = (const float*)d_in[4];
    const float* Wq_s  = (const float*)d_in[5];
    const float* Wk_s  = (const float*)d_in[6];
    const float* Wv_s  = (const float*)d_in[7];
    const float* Wq_v  = (const float*)d_in[8];
    const float* Wk_v  = (const float*)d_in[9];
    const float* Wv_v  = (const float*)d_in[10];
    const float* Wb    = (const float*)d_in[11];
    const float* bb    = (const float*)d_in[12];
    const float* Wdz   = (const float*)d_in[13];
    const float* bdz   = (const float*)d_in[14];
    const float* hw    = (const float*)d_in[15];
    const float* Wout  = (const float*)d_in[16];
    const float* bout  = (const float*)d_in[17];
    float* out = (float*)d_out;

    int N = in_sizes[0] / 64;
    int E = in_sizes[2] / 2;
    const int* ei = eidx;
    const int* ej = eidx + E;

    k_setup<<<(64 * 800 + 255) / 256, 256>>>(Wq_s, Wk_s, Wq_v, Wk_v, Wv_v, Wv_s, Wout);
    k_count<<<(E + 255) / 256, 256>>>(ei, E);
    k_scan<<<1, 1024>>>(N);
    k_scatter<<<(E + 255) / 256, 256>>>(ei, ej, E);

    dim3 gproj(13, (N + 127) / 128);
    k_gemm_proj<<<gproj, 256>>>(s, N);

    k_rotate<<<(N * 64 + 255) / 256, 256>>>(quat, trans, N);
    k_zproj<<<592, 256>>>(z, Wb, bb, Wdz, bdz, E);
    k_nf<<<(N + 7) / 8, 256>>>(s, hw, N);

    dim3 gout(1, (N + 63) / 64);
    k_gemm_out<<<gout, 256>>>(bout, out, N);
}

// round 13
// speedup vs baseline: 1.0133x; 1.0133x over previous
#include <cuda_runtime.h>
#include <cuda_bf16.h>
#include <math_constants.h>

#define NN 20000
#define EE 640000

#define SC_DOT 1.6329931618554521f     // sqrt(8/3)
#define SC_B   0.5773502691896258f     // sqrt(1/3)
#define SC_V   (-0.04811252243246881f) // -0.5*sqrt(1/108)

// ---- device scratch ----
__device__ __align__(16) float g_proj[(size_t)NN * 800]; // qs[0:256) ks[256:512) qv[512:608) kv[608:704) vv[704:800)
__device__ __align__(16) float g_qv[(size_t)NN * 96];
__device__ __align__(16) float g_kv[(size_t)NN * 96];
__device__ __align__(16) float g_zd[(size_t)EE * 20];    // CSR-ordered: [bias(4) | pz(16)] per edge
__device__ int   g_cnt[NN];
__device__ int   g_off[NN];
__device__ int   g_cur[NN];
__device__ int   g_pos[EE];      // e -> CSR slot
__device__ int   g_jsort[EE];    // CSR slot -> j
__device__ __align__(16) float g_fin[(size_t)NN * 160];  // [s(64) | norm(32) | pair(64)]
__device__ __align__(16) float g_Bproj[64 * 800];
__device__ __align__(16) float g_wcat[160 * 64];

// ---- merged setup: init counters + pack proj weights + fuse output weights ----
__global__ void k_setup(const float* __restrict__ Wq_s, const float* __restrict__ Wk_s,
                        const float* __restrict__ Wq_v, const float* __restrict__ Wk_v,
                        const float* __restrict__ Wv_v, const float* __restrict__ Wv_s,
                        const float* __restrict__ Wout) {
    int idx = blockIdx.x * blockDim.x + threadIdx.x;
    if (idx < NN) { g_cnt[idx] = 0; g_cur[idx] = 0; }
    if (idx < 64 * 800) {
        int d = idx / 800, c = idx % 800;
        float v;
        if (c < 256)      v = Wq_s[d * 256 + c];
        else if (c < 512) v = Wk_s[d * 256 + (c - 256)];
        else if (c < 608) v = Wq_v[d * 96 + (c - 512)];
        else if (c < 704) v = Wk_v[d * 96 + (c - 608)];
        else              v = Wv_v[d * 96 + (c - 704)];
        g_Bproj[idx] = v;
    }
    if (idx < 160 * 64) {
        int r = idx >> 6, c = idx & 63;
        if (r < 64) {
            float acc = 0.f;
            for (int k = 0; k < 256; k++) acc += Wv_s[r * 256 + k] * Wout[k * 64 + c];
            for (int k = 0; k < 96; k++)  acc += Wv_v[r * 96 + k] * Wout[(256 + k) * 64 + c];
            g_wcat[idx] = acc;
        } else if (r < 96) {
            g_wcat[idx] = Wout[(352 + (r - 64)) * 64 + c];
        } else {
            g_wcat[idx] = Wout[(384 + (r - 96)) * 64 + c];
        }
    }
}

__global__ void k_count(const int* __restrict__ ei, int E) {
    int e = blockIdx.x * blockDim.x + threadIdx.x;
    if (e < E) atomicAdd(&g_cnt[ei[e]], 1);
}

__global__ void k_scan(int n) {
    __shared__ int wsum[32];
    int tid = threadIdx.x;
    int per = (n + 1023) / 1024;
    int base = tid * per;
    int s = 0;
    for (int k = 0; k < per; k++) { int idx = base + k; if (idx < n) s += g_cnt[idx]; }
    int lane = tid & 31, w = tid >> 5;
    int v = s;
    #pragma unroll
    for (int o = 1; o < 32; o <<= 1) { int t = __shfl_up_sync(~0u, v, o); if (lane >= o) v += t; }
    if (lane == 31) wsum[w] = v;
    __syncthreads();
    if (w == 0) {
        int orig = wsum[lane], x = orig;
        #pragma unroll
        for (int o = 1; o < 32; o <<= 1) { int t = __shfl_up_sync(~0u, x, o); if (lane >= o) x += t; }
        wsum[lane] = x - orig;
    }
    __syncthreads();
    int run = v - s + wsum[w];
    for (int k = 0; k < per; k++) {
        int idx = base + k;
        if (idx < n) { g_off[idx] = run; run += g_cnt[idx]; }
    }
}

__global__ void k_scatter(const int* __restrict__ ei, const int* __restrict__ ej, int E) {
    int e = blockIdx.x * blockDim.x + threadIdx.x;
    if (e < E) {
        int i = ei[e];
        int p = atomicAdd(&g_cur[i], 1);
        int pos = g_off[i] + p;
        g_pos[e] = pos;
        g_jsort[pos] = ej[e];
    }
}

// ---- projection GEMM: g_proj[M,800] = s[M,64] @ g_Bproj[64,800] ----
__global__ void __launch_bounds__(256) k_gemm_proj(const float* __restrict__ A, int M) {
    __shared__ float4 As4[128][16];
    __shared__ float4 Bs4[64][16];
    const float* B = g_Bproj;
    int tid = threadIdx.x;
    int tx = tid & 15, ty = tid >> 4;
    int row0 = blockIdx.y * 128, col0 = blockIdx.x * 64;

    for (int i = tid; i < 128 * 16; i += 256) {
        int r = i >> 4, kq = i & 15;
        int gr = row0 + r;
        float4 av = make_float4(0.f, 0.f, 0.f, 0.f);
        if (gr < M) av = *(const float4*)(A + (size_t)gr * 64 + kq * 4);
        As4[r][kq] = av;
    }
    for (int i = tid; i < 64 * 16; i += 256) {
        int k = i >> 4, cq = i & 15;
        int gc = col0 + cq * 4;
        float4 bv = make_float4(0.f, 0.f, 0.f, 0.f);
        if (gc < 800) bv = *(const float4*)(B + (size_t)k * 800 + gc);
        Bs4[k][cq] = bv;
    }
    __syncthreads();

    float acc[8][4] = {};
    #pragma unroll
    for (int kq = 0; kq < 16; kq++) {
        float4 b0 = Bs4[kq * 4 + 0][tx];
        float4 b1 = Bs4[kq * 4 + 1][tx];
        float4 b2 = Bs4[kq * 4 + 2][tx];
        float4 b3 = Bs4[kq * 4 + 3][tx];
        #pragma unroll
        for (int i = 0; i < 8; i++) {
            float4 a = As4[ty * 8 + i][kq];
            acc[i][0] += a.x * b0.x + a.y * b1.x + a.z * b2.x + a.w * b3.x;
            acc[i][1] += a.x * b0.y + a.y * b1.y + a.z * b2.y + a.w * b3.y;
            acc[i][2] += a.x * b0.z + a.y * b1.z + a.z * b2.z + a.w * b3.z;
            acc[i][3] += a.x * b0.w + a.y * b1.w + a.z * b2.w + a.w * b3.w;
        }
    }
    int gc = col0 + tx * 4;
    if (gc < 800) {
        #pragma unroll
        for (int i = 0; i < 8; i++) {
            int gr = row0 + ty * 8 + i;
            if (gr < M) {
                *(float4*)(g_proj + (size_t)gr * 800 + gc) =
                    make_float4(acc[i][0], acc[i][1], acc[i][2], acc[i][3]);
            }
        }
    }
}

// ---- output GEMM: out[M,64] = g_fin[M,160] @ g_wcat[160,64] + bout ----
__global__ void k_gemm_out(const float* __restrict__ bout, float* __restrict__ out, int M) {
    __shared__ __align__(16) float As[64][17];
    __shared__ __align__(16) float Bs[16][64];
    const float* A = g_fin;
    const float* B = g_wcat;
    int tid = threadIdx.x;
    int tx = tid & 15, ty = tid >> 4;
    int row0 = blockIdx.y * 64;
    float acc[4][4] = {};
    int am = tid >> 2;
    int ak = (tid & 3) * 4;
    int bk = tid >> 6;
    int bn = tid & 63;

    for (int k0 = 0; k0 < 160; k0 += 16) {
        int gr = row0 + am;
        float4 av = make_float4(0.f, 0.f, 0.f, 0.f);
        if (gr < M) av = *(const float4*)(A + (size_t)gr * 160 + k0 + ak);
        As[am][ak + 0] = av.x; As[am][ak + 1] = av.y; As[am][ak + 2] = av.z; As[am][ak + 3] = av.w;
        #pragma unroll
        for (int l = 0; l < 4; l++) {
            int kk = bk + l * 4;
            Bs[kk][bn] = B[(size_t)(k0 + kk) * 64 + bn];
        }
        __syncthreads();
        #pragma unroll
        for (int kk = 0; kk < 16; kk++) {
            float a0 = As[ty * 4 + 0][kk], a1 = As[ty * 4 + 1][kk];
            float a2 = As[ty * 4 + 2][kk], a3 = As[ty * 4 + 3][kk];
            float4 bv = *(const float4*)&Bs[kk][tx * 4];
            acc[0][0] += a0 * bv.x; acc[0][1] += a0 * bv.y; acc[0][2] += a0 * bv.z; acc[0][3] += a0 * bv.w;
            acc[1][0] += a1 * bv.x; acc[1][1] += a1 * bv.y; acc[1][2] += a1 * bv.z; acc[1][3] += a1 * bv.w;
            acc[2][0] += a2 * bv.x; acc[2][1] += a2 * bv.y; acc[2][2] += a2 * bv.z; acc[2][3] += a2 * bv.w;
            acc[3][0] += a3 * bv.x; acc[3][1] += a3 * bv.y; acc[3][2] += a3 * bv.z; acc[3][3] += a3 * bv.w;
        }
        __syncthreads();
    }
    #pragma unroll
    for (int i = 0; i < 4; i++) {
        int gr = row0 + ty * 4 + i;
        if (gr >= M) continue;
        #pragma unroll
        for (int j = 0; j < 4; j++) {
            int gc = tx * 4 + j;
            out[(size_t)gr * 64 + gc] = acc[i][j] + bout[gc];
        }
    }
}

__global__ void k_rotate(const float* __restrict__ quat, const float* __restrict__ trans, int N) {
    int idx = blockIdx.x * blockDim.x + threadIdx.x;
    if (idx >= N * 64) return;
    int n = idx >> 6, t = idx & 63;
    int isQ = (t < 32);
    int c = t & 31;
    const float* src = g_proj + (size_t)n * 800 + (isQ ? 512 : 608);
    float vx = src[c], vy = src[32 + c], vz = src[64 + c];
    float qw = quat[n * 4 + 0], qx = quat[n * 4 + 1], qy = quat[n * 4 + 2], qz = quat[n * 4 + 3];
    float uvx = qy * vz - qz * vy;
    float uvy = qz * vx - qx * vz;
    float uvz = qx * vy - qy * vx;
    float rx = vx + 2.f * (qw * uvx + (qy * uvz - qz * uvy));
    float ry = vy + 2.f * (qw * uvy + (qz * uvx - qx * uvz));
    float rz = vz + 2.f * (qw * uvz + (qx * uvy - qy * uvx));
    float* dst = (isQ ? g_qv : g_kv) + (size_t)n * 96 + c * 3;
    dst[0] = rx + trans[n * 3 + 0];
    dst[1] = ry + trans[n * 3 + 1];
    dst[2] = rz + trans[n * 3 + 2];
}

// ---- z projections: bias(4 heads, scales folded) + pair_z(16), written at CSR pos ----
// warp per edge, grid-stride; all weights in registers
__global__ void __launch_bounds__(256) k_zproj(const float* __restrict__ z,
                       const float* __restrict__ Wb, const float* __restrict__ bb,
                       const float* __restrict__ Wdz, const float* __restrict__ bdz, int E) {
    int lane = threadIdx.x & 31;
    int gwarp = (blockIdx.x * blockDim.x + threadIdx.x) >> 5;
    int nwarp = (gridDim.x * blockDim.x) >> 5;
    int g = lane >> 3, r = lane & 7;
    int c16 = lane & 15, half = lane >> 4;

    // preload weights
    float wb[8];
    #pragma unroll
    for (int d = 0; d < 8; d++) wb[d] = Wb[(r * 8 + d) * 4 + g];
    float wd[32];
    #pragma unroll
    for (int d = 0; d < 32; d++) wd[d] = Wdz[(half * 32 + d) * 16 + c16];
    float bbg = SC_B * (bb[g]);
    float bdc = bdz[c16];

    for (int e = gwarp; e < E; e += nwarp) {
        int pos = g_pos[e];
        const float* zr = z + (size_t)e * 64;
        // bias: lane covers dims r*8..r*8+7 of head g
        float4 z0 = *(const float4*)(zr + r * 8);
        float4 z1 = *(const float4*)(zr + r * 8 + 4);
        float bias = z0.x * wb[0] + z0.y * wb[1] + z0.z * wb[2] + z0.w * wb[3]
                   + z1.x * wb[4] + z1.y * wb[5] + z1.z * wb[6] + z1.w * wb[7];
        bias += __shfl_xor_sync(~0u, bias, 1);
        bias += __shfl_xor_sync(~0u, bias, 2);
        bias += __shfl_xor_sync(~0u, bias, 4);
        // pz: lane covers dims half*32..+32, col c16
        float pc = 0.f;
        const float* zh = zr + half * 32;
        #pragma unroll
        for (int dq = 0; dq < 8; dq++) {
            float4 zv = *(const float4*)(zh + dq * 4);
            pc += zv.x * wd[dq * 4 + 0] + zv.y * wd[dq * 4 + 1]
                + zv.z * wd[dq * 4 + 2] + zv.w * wd[dq * 4 + 3];
        }
        pc += __shfl_xor_sync(~0u, pc, 16);
        float* rec = g_zd + (size_t)pos * 20;
        if (r == 0) rec[g] = SC_B * bias + bbg;
        if (lane < 16) rec[4 + c16] = pc + bdc;
    }
}

// ---- fused node kernel: warp per node, streaming online softmax + pair aggregation ----
__global__ void __launch_bounds__(256) k_nf(const float* __restrict__ s,
                                            const float* __restrict__ hw, int N) {
    int lane = threadIdx.x & 31, w = threadIdx.x >> 5;
    int n = blockIdx.x * 8 + w;
    if (n >= N) return;
    int off = g_off[n], deg = g_cnt[n];
    int g = lane >> 3, r = lane & 7;
    int c = lane & 15, hh = lane >> 4;

    // preload i-side data once per node
    const float* ksp = g_proj + (size_t)n * 800 + 256 + lane * 8;
    float4 k0 = *(const float4*)ksp;
    float4 k1 = *(const float4*)(ksp + 4);
    const float* qvp = g_qv + (size_t)n * 96 + lane * 3;
    float qvx = qvp[0], qvy = qvp[1], qvz = qvp[2];
    float svh = SC_V * log1pf(__expf(hw[g]));   // per-head softplus folded with scale

    // online softmax state: lane owns col c for heads hh and hh+2
    float m0 = -CUDART_INF_F, s0 = 0.f, P0 = 0.f;
    float m1 = -CUDART_INF_F, s1 = 0.f, P1 = 0.f;

    for (int t = 0; t < deg; t++) {
        int j = __ldg(&g_jsort[off + t]);
        // scalar dot partial
        const float* qsp = g_proj + (size_t)j * 800 + lane * 8;
        float4 q0 = *(const float4*)qsp;
        float4 q1 = *(const float4*)(qsp + 4);
        float part = k0.x * q0.x + k0.y * q0.y + k0.z * q0.z + k0.w * q0.w
                   + k1.x * q1.x + k1.y * q1.y + k1.z * q1.z + k1.w * q1.w;
        part *= SC_DOT;
        // point distance partial (point p = lane)
        const float* kvp = g_kv + (size_t)j * 96 + lane * 3;
        float dx = qvx - kvp[0], dy = qvy - kvp[1], dz = qvz - kvp[2];
        part += (dx * dx + dy * dy + dz * dz) * svh;
        // reduce within 8-lane head group
        part += __shfl_xor_sync(~0u, part, 1);
        part += __shfl_xor_sync(~0u, part, 2);
        part += __shfl_xor_sync(~0u, part, 4);
        // fetch logits for the two heads this lane accumulates
        const float* rec = g_zd + (size_t)(off + t) * 20;
        float l0 = __shfl_sync(~0u, part, hh * 8)       + __ldg(&rec[hh]);
        float l1 = __shfl_sync(~0u, part, (hh + 2) * 8) + __ldg(&rec[hh + 2]);
        float pz = __ldg(&rec[4 + c]);
        // online update head hh
        float mn0 = fmaxf(m0, l0);
        float sc0 = __expf(m0 - mn0), w0 = __expf(l0 - mn0);
        s0 = s0 * sc0 + w0; P0 = P0 * sc0 + w0 * pz; m0 = mn0;
        // online update head hh+2
        float mn1 = fmaxf(m1, l1);
        float sc1 = __expf(m1 - mn1), w1 = __expf(l1 - mn1);
        s1 = s1 * sc1 + w1; P1 = P1 * sc1 + w1 * pz; m1 = mn1;
    }
    float i0 = (s0 > 0.f) ? (1.f / s0) : 0.f;
    float i1 = (s1 > 0.f) ? (1.f / s1) : 0.f;

    float* fin = g_fin + (size_t)n * 160;
    fin[96 + hh * 16 + c] = P0 * i0;
    fin[96 + (hh + 2) * 16 + c] = P1 * i1;

    // s copy + vv point norms
    float2 sv = ((const float2*)(s + (size_t)n * 64))[lane];
    ((float2*)fin)[lane] = sv;
    const float* vv = g_proj + (size_t)n * 800 + 704;
    float px = vv[lane], py = vv[32 + lane], pz2 = vv[64 + lane];
    fin[64 + lane] = sqrtf(px * px + py * py + pz2 * pz2 + 1e-8f);
}

extern "C" void kernel_launch(void* const* d_in, const int* in_sizes, int n_in,
                              void* d_out, int out_size) {
    const float* s     = (const float*)d_in[0];
    const float* z     = (const float*)d_in[1];
    const int*   eidx  = (const int*)d_in[2];
    const float* quat  = (const float*)d_in[3];
    const float* trans = (const float*)d_in[4];
    const float* Wq_s  = (const float*)d_in[5];
    const float* Wk_s  = (const float*)d_in[6];
    const float* Wv_s  = (const float*)d_in[7];
    const float* Wq_v  = (const float*)d_in[8];
    const float* Wk_v  = (const float*)d_in[9];
    const float* Wv_v  = (const float*)d_in[10];
    const float* Wb    = (const float*)d_in[11];
    const float* bb    = (const float*)d_in[12];
    const float* Wdz   = (const float*)d_in[13];
    const float* bdz   = (const float*)d_in[14];
    const float* hw    = (const float*)d_in[15];
    const float* Wout  = (const float*)d_in[16];
    const float* bout  = (const float*)d_in[17];
    float* out = (float*)d_out;

    int N = in_sizes[0] / 64;
    int E = in_sizes[2] / 2;
    const int* ei = eidx;
    const int* ej = eidx + E;

    k_setup<<<(64 * 800 + 255) / 256, 256>>>(Wq_s, Wk_s, Wq_v, Wk_v, Wv_v, Wv_s, Wout);
    k_count<<<(E + 255) / 256, 256>>>(ei, E);
    k_scan<<<1, 1024>>>(N);
    k_scatter<<<(E + 255) / 256, 256>>>(ei, ej, E);

    dim3 gproj(13, (N + 127) / 128);
    k_gemm_proj<<<gproj, 256>>>(s, N);

    k_rotate<<<(N * 64 + 255) / 256, 256>>>(quat, trans, N);
    k_zproj<<<592, 256>>>(z, Wb, bb, Wdz, bdz, E);
    k_nf<<<(N + 7) / 8, 256>>>(s, hw, N);

    dim3 gout(1, (N + 63) / 64);
    k_gemm_out<<<gout, 256>>>(bout, out, N);
}